// round 1
// baseline (speedup 1.0000x reference)
#include <cuda_runtime.h>
#include <math.h>

// Problem constants
#define Bb   16
#define Tt   2048
#define Cc   512
#define Hh   4
#define DHd  128
#define Nn   (Bb*Tt)    // 32768 tokens
#define N2   (Nn*2)     // 65536 token-device rows

// ---------------- device scratch (no allocations allowed) ----------------
__device__ float g_QKV[N2 * 1536];      // 400 MB: q|k|v per token-device row
__device__ float g_ctx[N2 * 512];       // 134 MB: attention context
__device__ float g_tmp[512 * 512];      // fold scratch
__device__ float g_Mcat[512 * 1024];    // [M0 | M1] folded post-attention weights
__device__ float g_u[2 * 512];          // folded bias intermediates
__device__ float g_bconst[512];         // folded output bias

// =========================================================================
// Fold kernels: M0 = WoutL @ Wp @ Wo, M1 = WoutR @ Wi @ Wo, bconst
// =========================================================================

// Generic 512x512x512 row-major GEMM: C[m,n] = sum_k A[m*lda+k] * B[k*512+n]
__global__ void k_fold_gemm(const float* __restrict__ A, int lda,
                            const float* __restrict__ Bm,
                            int useTmpB, int writeMcat, int coff)
{
    __shared__ float As[32][33];
    __shared__ float Bs[32][33];
    const float* Bp = useTmpB ? g_tmp : Bm;
    float* Cp;
    int ldc;
    if (writeMcat) { Cp = g_Mcat + coff; ldc = 1024; }
    else           { Cp = g_tmp;         ldc = 512;  }

    int tx = threadIdx.x, ty = threadIdx.y;
    int row = blockIdx.y * 32 + ty;
    int col = blockIdx.x * 32 + tx;
    float acc = 0.f;
    for (int k0 = 0; k0 < 512; k0 += 32) {
        As[ty][tx] = A[row * lda + k0 + tx];
        Bs[ty][tx] = Bp[(k0 + ty) * 512 + col];
        __syncthreads();
        #pragma unroll
        for (int kk = 0; kk < 32; kk++) acc += As[ty][kk] * Bs[kk][tx];
        __syncthreads();
    }
    Cp[row * ldc + col] = acc;
}

// u[d][j] = sum_l W_d[j,l]*out_proj_b[l] + b_d[j]   (d=0: phone, d=1: imu)
__global__ void k_fold_u(const float* __restrict__ phone_w, const float* __restrict__ phone_b,
                         const float* __restrict__ imu_w,   const float* __restrict__ imu_b,
                         const float* __restrict__ out_proj_b)
{
    int idx = blockIdx.x * blockDim.x + threadIdx.x;
    if (idx >= 1024) return;
    int d = idx >> 9, j = idx & 511;
    const float* W  = d ? imu_w : phone_w;
    const float* bb = d ? imu_b : phone_b;
    float s = bb[j];
    for (int l = 0; l < 512; l++) s += W[j * 512 + l] * out_proj_b[l];
    g_u[idx] = s;
}

// bconst[o] = WoutL[o,:].u0 + WoutR[o,:].u1 + output_b[o]; also zero avg region
__global__ void k_fold_bconst(const float* __restrict__ output_w,
                              const float* __restrict__ output_b,
                              float* __restrict__ d_avg)
{
    int o = blockIdx.x * blockDim.x + threadIdx.x;
    if (o < 64) d_avg[o] = 0.f;
    if (o >= 512) return;
    float s = output_b[o];
    for (int j = 0; j < 512; j++) {
        s += output_w[o * 1024 + j]       * g_u[j];
        s += output_w[o * 1024 + 512 + j] * g_u[512 + j];
    }
    g_bconst[o] = s;
}

// =========================================================================
// GEMM1: QKV = (x transposed + emb) @ in_proj_w^T + in_proj_b
//   rows = token-device pairs; A-tile built on the fly from x (B,C,2,T)
//   tile: 128 rows (64 tokens x 2 dev, dev-major) x 128 cols, BK=16
// =========================================================================
__global__ __launch_bounds__(256) void k_qkv(const float* __restrict__ x,
                                             const float* __restrict__ emb,
                                             const float* __restrict__ W,
                                             const float* __restrict__ bias)
{
    __shared__ float As[16][132];
    __shared__ float Bs[16][132];
    int tid = threadIdx.x;
    int n0 = blockIdx.y * 64;        // first token of tile (never crosses batch: 2048 % 64 == 0)
    int j0 = blockIdx.x * 128;
    int b  = n0 >> 11;
    int t0 = n0 & 2047;

    int ar = tid & 127;              // tile row for A loads
    int d  = ar >> 6, tl = ar & 63;
    const float* xbase = x + (size_t)b * 2097152 + d * 2048 + t0 + tl;
    const float* embd  = emb + d * 512;
    int ka = tid >> 7;               // 0/1
    int kb = tid & 15;
    int jb = tid >> 4;               // 0..15
    int ty = tid >> 4, tx = tid & 15;

    float acc[8][8];
    #pragma unroll
    for (int i = 0; i < 8; i++)
        #pragma unroll
        for (int j = 0; j < 8; j++) acc[i][j] = 0.f;

    for (int k0 = 0; k0 < 512; k0 += 16) {
        #pragma unroll
        for (int i = 0; i < 8; i++) {
            int kk = ka + i * 2;
            int c  = k0 + kk;
            As[kk][ar] = __ldg(&xbase[(size_t)c * 4096]) + embd[c];
        }
        #pragma unroll
        for (int i = 0; i < 8; i++) {
            int j = jb + i * 16;
            Bs[kb][j] = W[(size_t)(j0 + j) * 512 + k0 + kb];
        }
        __syncthreads();
        #pragma unroll
        for (int kk = 0; kk < 16; kk++) {
            float a[8], bv[8];
            *(float4*)&a[0]  = *(const float4*)&As[kk][ty * 8];
            *(float4*)&a[4]  = *(const float4*)&As[kk][ty * 8 + 4];
            *(float4*)&bv[0] = *(const float4*)&Bs[kk][tx * 8];
            *(float4*)&bv[4] = *(const float4*)&Bs[kk][tx * 8 + 4];
            #pragma unroll
            for (int i = 0; i < 8; i++)
                #pragma unroll
                for (int j = 0; j < 8; j++) acc[i][j] += a[i] * bv[j];
        }
        __syncthreads();
    }
    #pragma unroll
    for (int i = 0; i < 8; i++) {
        int r  = ty * 8 + i;
        int n2 = 2 * (n0 + (r & 63)) + (r >> 6);
        float* outp = g_QKV + (size_t)n2 * 1536 + j0 + tx * 8;
        #pragma unroll
        for (int j = 0; j < 8; j++)
            outp[j] = acc[i][j] + bias[j0 + tx * 8 + j];
    }
}

// =========================================================================
// Attention: per (token, head) — 2x2 scores, softmax, ctx = P @ V
// 256 threads = 2 tokens x 4 heads(warps). Also accumulate avg_attention.
// =========================================================================
__global__ __launch_bounds__(256) void k_attn(float* __restrict__ d_avg)
{
    __shared__ float sp[4];
    int tid = threadIdx.x;
    if (tid < 4) sp[tid] = 0.f;
    __syncthreads();

    int n    = blockIdx.x * 2 + (tid >> 7);
    int h    = (tid >> 5) & 3;
    int lane = tid & 31;

    const float* base = g_QKV + (size_t)(2 * n) * 1536 + h * 128 + lane * 4;
    float4 q0  = *(const float4*)(base);
    float4 q1  = *(const float4*)(base + 1536);
    float4 k0v = *(const float4*)(base + 512);
    float4 k1v = *(const float4*)(base + 512 + 1536);
    float4 v0  = *(const float4*)(base + 1024);
    float4 v1  = *(const float4*)(base + 1024 + 1536);

    float s00 = q0.x*k0v.x + q0.y*k0v.y + q0.z*k0v.z + q0.w*k0v.w;
    float s01 = q0.x*k1v.x + q0.y*k1v.y + q0.z*k1v.z + q0.w*k1v.w;
    float s10 = q1.x*k0v.x + q1.y*k0v.y + q1.z*k0v.z + q1.w*k0v.w;
    float s11 = q1.x*k1v.x + q1.y*k1v.y + q1.z*k1v.z + q1.w*k1v.w;
    #pragma unroll
    for (int off = 16; off; off >>= 1) {
        s00 += __shfl_xor_sync(0xffffffffu, s00, off);
        s01 += __shfl_xor_sync(0xffffffffu, s01, off);
        s10 += __shfl_xor_sync(0xffffffffu, s10, off);
        s11 += __shfl_xor_sync(0xffffffffu, s11, off);
    }
    const float sc = 0.08838834764831845f;   // 1/sqrt(128)
    s00 *= sc; s01 *= sc; s10 *= sc; s11 *= sc;

    float m0 = fmaxf(s00, s01);
    float e00 = expf(s00 - m0), e01 = expf(s01 - m0);
    float r0 = 1.f / (e00 + e01);
    float p00 = e00 * r0, p01 = e01 * r0;
    float m1 = fmaxf(s10, s11);
    float e10 = expf(s10 - m1), e11 = expf(s11 - m1);
    float r1 = 1.f / (e10 + e11);
    float p10 = e10 * r1, p11 = e11 * r1;

    float* ctxp = g_ctx + (size_t)(2 * n) * 512 + h * 128 + lane * 4;
    float4 c0, c1;
    c0.x = p00*v0.x + p01*v1.x; c0.y = p00*v0.y + p01*v1.y;
    c0.z = p00*v0.z + p01*v1.z; c0.w = p00*v0.w + p01*v1.w;
    c1.x = p10*v0.x + p11*v1.x; c1.y = p10*v0.y + p11*v1.y;
    c1.z = p10*v0.z + p11*v1.z; c1.w = p10*v0.w + p11*v1.w;
    *(float4*)ctxp         = c0;
    *(float4*)(ctxp + 512) = c1;

    if (lane == 0) {
        atomicAdd(&sp[0], p00);
        atomicAdd(&sp[1], p01);
        atomicAdd(&sp[2], p10);
        atomicAdd(&sp[3], p11);
    }
    __syncthreads();
    if (tid < 4) {
        int b = (blockIdx.x * 2) >> 11;           // both tokens share b
        atomicAdd(&d_avg[b * 4 + tid], sp[tid] * (1.0f / 8192.0f));  // / (H*T)
    }
}

// =========================================================================
// GEMM2: out[n,o] = ctx(N x 1024) @ Mcat^T + bconst; written as (B,C,T)
//   tile: 128 tokens x 128 output cols, K=1024, BK=16
// =========================================================================
__global__ __launch_bounds__(256) void k_out(float* __restrict__ out)
{
    __shared__ float As[16][132];
    __shared__ float Bs[16][132];
    int tid = threadIdx.x;
    int n0 = blockIdx.y * 128;       // 2048 % 128 == 0 -> never crosses batch
    int o0 = blockIdx.x * 128;
    int kb = tid & 15;
    int rb = tid >> 4;
    int ty = tid >> 4, tx = tid & 15;

    float acc[8][8];
    #pragma unroll
    for (int i = 0; i < 8; i++)
        #pragma unroll
        for (int j = 0; j < 8; j++) acc[i][j] = 0.f;

    for (int k0 = 0; k0 < 1024; k0 += 16) {
        #pragma unroll
        for (int i = 0; i < 8; i++) {
            int r = rb + i * 16;
            As[kb][r] = g_ctx [(size_t)(n0 + r) * 1024 + k0 + kb];
            Bs[kb][r] = g_Mcat[(size_t)(o0 + r) * 1024 + k0 + kb];
        }
        __syncthreads();
        #pragma unroll
        for (int kk = 0; kk < 16; kk++) {
            float a[8], bv[8];
            *(float4*)&a[0]  = *(const float4*)&As[kk][ty * 8];
            *(float4*)&a[4]  = *(const float4*)&As[kk][ty * 8 + 4];
            *(float4*)&bv[0] = *(const float4*)&Bs[kk][tx * 8];
            *(float4*)&bv[4] = *(const float4*)&Bs[kk][tx * 8 + 4];
            #pragma unroll
            for (int i = 0; i < 8; i++)
                #pragma unroll
                for (int j = 0; j < 8; j++) acc[i][j] += a[i] * bv[j];
        }
        __syncthreads();
    }
    int b  = n0 >> 11;
    int t0 = n0 & 2047;
    #pragma unroll
    for (int i = 0; i < 8; i++) {
        int t = t0 + ty * 8 + i;
        #pragma unroll
        for (int j = 0; j < 8; j++) {
            int o = o0 + tx * 8 + j;
            out[(size_t)b * 1048576 + (size_t)o * 2048 + t] = acc[i][j] + g_bconst[o];
        }
    }
}

// =========================================================================
extern "C" void kernel_launch(void* const* d_in, const int* in_sizes, int n_in,
                              void* d_out, int out_size)
{
    (void)in_sizes; (void)n_in; (void)out_size;
    const float* x      = (const float*)d_in[0];
    const float* emb    = (const float*)d_in[1];
    const float* in_w   = (const float*)d_in[2];
    const float* in_b   = (const float*)d_in[3];
    const float* out_w  = (const float*)d_in[4];
    const float* out_b  = (const float*)d_in[5];
    const float* ph_w   = (const float*)d_in[6];
    const float* ph_b   = (const float*)d_in[7];
    const float* im_w   = (const float*)d_in[8];
    const float* im_b   = (const float*)d_in[9];
    const float* o2_w   = (const float*)d_in[10];
    const float* o2_b   = (const float*)d_in[11];
    float* out   = (float*)d_out;
    float* d_avg = out + (size_t)Bb * Cc * Tt;   // avg_attention after main output

    dim3 fg(16, 16), fb(32, 32);
    // T0 = phone_w @ out_proj_w -> tmp ; M0 = WoutL @ T0 -> Mcat[:, :512]
    k_fold_gemm<<<fg, fb>>>(ph_w, 512, out_w, 0, 0, 0);
    k_fold_gemm<<<fg, fb>>>(o2_w, 1024, nullptr, 1, 1, 0);
    // T1 = imu_w @ out_proj_w -> tmp ; M1 = WoutR @ T1 -> Mcat[:, 512:]
    k_fold_gemm<<<fg, fb>>>(im_w, 512, out_w, 0, 0, 0);
    k_fold_gemm<<<fg, fb>>>(o2_w + 512, 1024, nullptr, 1, 1, 512);
    // folded biases + zero avg region
    k_fold_u<<<4, 256>>>(ph_w, ph_b, im_w, im_b, out_b);
    k_fold_bconst<<<2, 256>>>(o2_w, o2_b, d_avg);

    // main pipeline
    k_qkv <<<dim3(12, 512), 256>>>(x, emb, in_w, in_b);
    k_attn<<<Nn / 2, 256>>>(d_avg);
    k_out <<<dim3(4, 256), 256>>>(out);
}